// round 5
// baseline (speedup 1.0000x reference)
#include <cuda_runtime.h>
#include <cstdint>

#define B_  4
#define L_  2048
#define D_  512
#define DK_ 256

// Scratch (allocation-free per harness rules)
__device__ float g_Q[B_ * L_ * DK_];
__device__ float g_K[B_ * L_ * DK_];
__device__ float g_V[B_ * L_ * D_];
__device__ float g_QE[(size_t)B_ * L_ * L_];
__device__ float g_S[(size_t)B_ * L_ * L_];

__device__ __forceinline__ uint32_t cvt_tf32(float x) {
    uint32_t r;
    asm("cvt.rna.tf32.f32 %0, %1;" : "=r"(r) : "f"(x));
    return r;
}

__device__ __forceinline__ void mma_tf32(float c[4], const uint32_t a[4], const uint32_t b[2]) {
    asm volatile(
        "mma.sync.aligned.m16n8k8.row.col.f32.tf32.tf32.f32 "
        "{%0,%1,%2,%3},{%4,%5,%6,%7},{%8,%9},{%0,%1,%2,%3};"
        : "+f"(c[0]), "+f"(c[1]), "+f"(c[2]), "+f"(c[3])
        : "r"(a[0]), "r"(a[1]), "r"(a[2]), "r"(a[3]), "r"(b[0]), "r"(b[1]));
}

// ---------------------------------------------------------------------------
// TF32 tensor-core GEMM. Block tile 128x128, K-chunk 32, 256 threads = 8 warps
// (2x4 warp grid, warp tile 64x32). fp32 accumulate.
//
// K-side operand tiles (A always; B when TRANS_B) use a k-interleaved smem
// layout: within each 8-k group, position 2c / 2c+1 holds k=c / k=c+4, row
// stride 40 words. Fragment loads are then single conflict-free LDS.64.
//
//   TRANS_B=false: C = A[M,K] * B[K,N]           (row-major B)
//   TRANS_B=true : C = A[M,K] * B[N,K]^T
//   SKEW=true    : C = (A*B^T + skew(QE)) * 1/16 (QK^T epilogue)
// ---------------------------------------------------------------------------
template <bool TRANS_B, bool SKEW>
__global__ __launch_bounds__(256)
void tgemm(const float* __restrict__ A, const float* __restrict__ Bm,
           float* __restrict__ C, int M, int N, int Kd,
           long long sA, long long sB, long long sC,
           const float* __restrict__ QE)
{
    __shared__ uint32_t As[128 * 40];                       // interleaved [m][k']
    __shared__ uint32_t Bs[TRANS_B ? (128 * 40) : (32 * 136)];

    const int bz = blockIdx.z;
    A  += (size_t)bz * sA;
    Bm += (size_t)bz * sB;
    C  += (size_t)bz * sC;

    const int bm = blockIdx.y * 128;
    const int bn = blockIdx.x * 128;
    const int tid  = threadIdx.x;
    const int lane = tid & 31;
    const int warp = tid >> 5;
    const int wm = warp & 1;   // 0..1  (64-row slab)
    const int wn = warp >> 1;  // 0..3  (32-col slab)

    // K-side tile global/store mapping: 32 rows x 4 row-blocks, 8 threads/row
    const int arow = tid >> 3;                   // 0..31
    const int t7   = tid & 7;
    const int akg  = (t7 >> 1) * 8 + (t7 & 1) * 2;   // global k offset (loads k, k+1, k+4, k+5)
    const int apos = (t7 >> 1) * 8 + (t7 & 1) * 4;   // interleaved smem word offset
    // NN B tile: 32x128 floats, [k][n] stride 136
    const int brow  = tid >> 5;          // 0..7
    const int bcol4 = (tid & 31) << 2;   // 0..124

    float acc[4][4][4];
#pragma unroll
    for (int i = 0; i < 4; i++)
#pragma unroll
        for (int j = 0; j < 4; j++)
#pragma unroll
            for (int e = 0; e < 4; e++) acc[i][j][e] = 0.f;

    float2 la[4], ha[4], lb[4], hb[4];
    float4 rbn[4];

    // ---- prologue global load (k0 = 0) ----
#pragma unroll
    for (int i = 0; i < 4; i++) {
        const float* p = A + (size_t)(bm + arow + 32 * i) * Kd + akg;
        la[i] = *reinterpret_cast<const float2*>(p);
        ha[i] = *reinterpret_cast<const float2*>(p + 4);
    }
#pragma unroll
    for (int i = 0; i < 4; i++) {
        if (TRANS_B) {
            const float* p = Bm + (size_t)(bn + arow + 32 * i) * Kd + akg;
            lb[i] = *reinterpret_cast<const float2*>(p);
            hb[i] = *reinterpret_cast<const float2*>(p + 4);
        } else {
            rbn[i] = *reinterpret_cast<const float4*>(
                Bm + (size_t)(brow + 8 * i) * N + bn + bcol4);
        }
    }

    for (int k0 = 0; k0 < Kd; k0 += 32) {
        // ---- store tiles to smem (interleaved pack {k, k+4, k+1, k+5}) ----
#pragma unroll
        for (int i = 0; i < 4; i++) {
            *reinterpret_cast<uint4*>(&As[(arow + 32 * i) * 40 + apos]) =
                make_uint4(cvt_tf32(la[i].x), cvt_tf32(ha[i].x),
                           cvt_tf32(la[i].y), cvt_tf32(ha[i].y));
        }
#pragma unroll
        for (int i = 0; i < 4; i++) {
            if (TRANS_B) {
                *reinterpret_cast<uint4*>(&Bs[(arow + 32 * i) * 40 + apos]) =
                    make_uint4(cvt_tf32(lb[i].x), cvt_tf32(hb[i].x),
                               cvt_tf32(lb[i].y), cvt_tf32(hb[i].y));
            } else {
                *reinterpret_cast<uint4*>(&Bs[(brow + 8 * i) * 136 + bcol4]) =
                    make_uint4(cvt_tf32(rbn[i].x), cvt_tf32(rbn[i].y),
                               cvt_tf32(rbn[i].z), cvt_tf32(rbn[i].w));
            }
        }
        __syncthreads();

        // ---- prefetch next chunk into registers ----
        if (k0 + 32 < Kd) {
            const int kn = k0 + 32;
#pragma unroll
            for (int i = 0; i < 4; i++) {
                const float* p = A + (size_t)(bm + arow + 32 * i) * Kd + kn + akg;
                la[i] = *reinterpret_cast<const float2*>(p);
                ha[i] = *reinterpret_cast<const float2*>(p + 4);
            }
#pragma unroll
            for (int i = 0; i < 4; i++) {
                if (TRANS_B) {
                    const float* p = Bm + (size_t)(bn + arow + 32 * i) * Kd + kn + akg;
                    lb[i] = *reinterpret_cast<const float2*>(p);
                    hb[i] = *reinterpret_cast<const float2*>(p + 4);
                } else {
                    rbn[i] = *reinterpret_cast<const float4*>(
                        Bm + (size_t)(kn + brow + 8 * i) * N + bn + bcol4);
                }
            }
        }

        // ---- compute: 4 k8-steps ----
        const int fm  = wm * 64 + (lane >> 2);
        const int fc2 = 2 * (lane & 3);
#pragma unroll
        for (int kb = 0; kb < 4; kb++) {
            const int kw = kb * 8 + fc2;
            uint32_t af[4][4];
#pragma unroll
            for (int mi = 0; mi < 4; mi++) {
                uint2 lo = *reinterpret_cast<const uint2*>(&As[(fm + mi * 16) * 40 + kw]);
                uint2 hi = *reinterpret_cast<const uint2*>(&As[(fm + mi * 16 + 8) * 40 + kw]);
                af[mi][0] = lo.x; af[mi][1] = hi.x; af[mi][2] = lo.y; af[mi][3] = hi.y;
            }
            uint32_t bf[4][2];
#pragma unroll
            for (int ni = 0; ni < 4; ni++) {
                const int n = wn * 32 + ni * 8 + (lane >> 2);
                if (TRANS_B) {
                    uint2 bb = *reinterpret_cast<const uint2*>(&Bs[n * 40 + kw]);
                    bf[ni][0] = bb.x; bf[ni][1] = bb.y;
                } else {
                    bf[ni][0] = Bs[(kb * 8 + (lane & 3)) * 136 + n];
                    bf[ni][1] = Bs[(kb * 8 + 4 + (lane & 3)) * 136 + n];
                }
            }
#pragma unroll
            for (int mi = 0; mi < 4; mi++)
#pragma unroll
                for (int ni = 0; ni < 4; ni++)
                    mma_tf32(acc[mi][ni], af[mi], bf[ni]);
        }
        __syncthreads();
    }

    // ---- epilogue ----
    if (!SKEW) {
#pragma unroll
        for (int mi = 0; mi < 4; mi++) {
            const int r0 = bm + wm * 64 + mi * 16 + (lane >> 2);
#pragma unroll
            for (int ni = 0; ni < 4; ni++) {
                const int c0 = bn + wn * 32 + ni * 8 + 2 * (lane & 3);
                *reinterpret_cast<float2*>(C + (size_t)r0 * N + c0) =
                    make_float2(acc[mi][ni][0], acc[mi][ni][1]);
                *reinterpret_cast<float2*>(C + (size_t)(r0 + 8) * N + c0) =
                    make_float2(acc[mi][ni][2], acc[mi][ni][3]);
            }
        }
    } else {
        // Srel[l,m] = QE[l, m-l+L-1] (m<=l); 0 (m==l+1); QE[l+1, m-l-2] (m>=l+2)
        const float scale = 0.0625f;  // 1/sqrt(256)
        const int b = blockIdx.z;
#pragma unroll
        for (int mi = 0; mi < 4; mi++) {
            const int rbase = bm + wm * 64 + mi * 16 + (lane >> 2);
#pragma unroll
            for (int ni = 0; ni < 4; ni++) {
                const int c0 = bn + wn * 32 + ni * 8 + 2 * (lane & 3);
#pragma unroll
                for (int h = 0; h < 2; h++) {
                    const int l = rbase + 8 * h;
                    const size_t row0 = (size_t)(b * L_ + l) * L_;
                    const size_t row1 = (size_t)(b * L_ + l + 1) * L_;
                    float out[2];
#pragma unroll
                    for (int e = 0; e < 2; e++) {
                        const int m = c0 + e;
                        float srel;
                        if (m <= l)          srel = QE[row0 + (m - l + L_ - 1)];
                        else if (m == l + 1) srel = 0.f;
                        else                 srel = QE[row1 + (m - l - 2)];
                        out[e] = (acc[mi][ni][2 * h + e] + srel) * scale;
                    }
                    *reinterpret_cast<float2*>(C + (size_t)l * N + c0) =
                        make_float2(out[0], out[1]);
                }
            }
        }
    }
}

// ---------------------------------------------------------------------------
// Row softmax over 2048 elements: one block per row, 256 threads x 8 elements.
// ---------------------------------------------------------------------------
__global__ void softmax2048(float* __restrict__ S)
{
    __shared__ float red[8];
    const size_t row = blockIdx.x;
    float* p = S + row * (size_t)L_;
    const int tid = threadIdx.x;

    float v[8];
    float mx = -1e30f;
#pragma unroll
    for (int i = 0; i < 8; i++) {
        v[i] = p[tid + i * 256];
        mx = fmaxf(mx, v[i]);
    }
#pragma unroll
    for (int o = 16; o > 0; o >>= 1)
        mx = fmaxf(mx, __shfl_xor_sync(0xffffffffu, mx, o));
    if ((tid & 31) == 0) red[tid >> 5] = mx;
    __syncthreads();
    mx = red[0];
#pragma unroll
    for (int w = 1; w < 8; w++) mx = fmaxf(mx, red[w]);
    __syncthreads();

    float sum = 0.f;
#pragma unroll
    for (int i = 0; i < 8; i++) {
        v[i] = __expf(v[i] - mx);
        sum += v[i];
    }
#pragma unroll
    for (int o = 16; o > 0; o >>= 1)
        sum += __shfl_xor_sync(0xffffffffu, sum, o);
    if ((tid & 31) == 0) red[tid >> 5] = sum;
    __syncthreads();
    float tot = 0.f;
#pragma unroll
    for (int w = 0; w < 8; w++) tot += red[w];

    const float inv = 1.f / tot;
#pragma unroll
    for (int i = 0; i < 8; i++) p[tid + i * 256] = v[i] * inv;
}

// ---------------------------------------------------------------------------
extern "C" void kernel_launch(void* const* d_in, const int* in_sizes, int n_in,
                              void* d_out, int out_size)
{
    const float* inQ = (const float*)d_in[0];
    const float* inK = (const float*)d_in[1];
    const float* inV = (const float*)d_in[2];
    const float* Wq  = (const float*)d_in[3];
    const float* Wk  = (const float*)d_in[4];
    const float* Wv  = (const float*)d_in[5];
    const float* E   = (const float*)d_in[6];
    float* out = (float*)d_out;

    float *Q, *K, *V, *QE, *S;
    cudaGetSymbolAddress((void**)&Q,  g_Q);
    cudaGetSymbolAddress((void**)&K,  g_K);
    cudaGetSymbolAddress((void**)&V,  g_V);
    cudaGetSymbolAddress((void**)&QE, g_QE);
    cudaGetSymbolAddress((void**)&S,  g_S);

    const int BL = B_ * L_;  // 8192

    // Projections: [8192,512] x [512,{256,256,512}] (NN)
    tgemm<false, false><<<dim3(DK_ / 128, BL / 128, 1), 256>>>(
        inQ, Wq, Q, BL, DK_, D_, 0, 0, 0, nullptr);
    tgemm<false, false><<<dim3(DK_ / 128, BL / 128, 1), 256>>>(
        inK, Wk, K, BL, DK_, D_, 0, 0, 0, nullptr);
    tgemm<false, false><<<dim3(D_ / 128, BL / 128, 1), 256>>>(
        inV, Wv, V, BL, D_, D_, 0, 0, 0, nullptr);

    // QE = Q * E^T : [8192,256] x [2048,256]^T -> [8192,2048] (NT)
    tgemm<true, false><<<dim3(L_ / 128, BL / 128, 1), 256>>>(
        Q, E, QE, BL, L_, DK_, 0, 0, 0, nullptr);

    // S = (Q K^T + skew(QE)) / 16, batched over B (NT + skew epilogue)
    tgemm<true, true><<<dim3(L_ / 128, L_ / 128, B_), 256>>>(
        Q, K, S, L_, L_, DK_,
        (long long)L_ * DK_, (long long)L_ * DK_, (long long)L_ * L_, QE);

    // softmax along rows
    softmax2048<<<BL, 256>>>(S);

    // out = P * V, batched over B: [2048,2048] x [2048,512] (NN)
    tgemm<false, false><<<dim3(D_ / 128, L_ / 128, B_), 256>>>(
        S, V, out, L_, D_, L_,
        (long long)L_ * L_, (long long)L_ * D_, (long long)L_ * D_, nullptr);
}